// round 1
// baseline (speedup 1.0000x reference)
#include <cuda_runtime.h>
#include <math.h>

// Shapes (fixed by problem)
#define BB 8
#define LL 256
#define DM 256
#define DS 16
#define DI 512
#define DTR 16
#define DCV 4
#define MROWS (BB*LL)      // 2048

// ---------------- scratch (device globals; no allocation allowed) ------------
__device__ float g_lnx [2][MROWS*DM];
__device__ float g_xz  [2][MROWS*2*DI];
__device__ float g_xc  [2][MROWS*DI];
__device__ float g_dt  [2][MROWS*DI];
__device__ float g_xdbl[2][MROWS*(DTR+2*DS)];
__device__ float g_y   [2][MROWS*DI];
__device__ float g_ab  [2][MROWS*DM];
__device__ float g_id  [2][MROWS*DM];
__device__ float g_tmp [2][MROWS*DM];
__device__ float g_pool[BB*DM];
__device__ float g_fw  [BB*DM];

// ---------------- LayerNorm over last dim (=256) ----------------------------
__global__ void ln_kernel(const float* __restrict__ x, const float* __restrict__ g,
                          const float* __restrict__ b, float* __restrict__ out, float eps)
{
    int row = blockIdx.x, tid = threadIdx.x;
    __shared__ float sh[DM];
    float v = x[row*DM + tid];
    sh[tid] = v; __syncthreads();
    for (int s = DM/2; s > 0; s >>= 1) { if (tid < s) sh[tid] += sh[tid+s]; __syncthreads(); }
    float mu = sh[0] * (1.f/DM);
    __syncthreads();
    float dv = v - mu;
    sh[tid] = dv*dv; __syncthreads();
    for (int s = DM/2; s > 0; s >>= 1) { if (tid < s) sh[tid] += sh[tid+s]; __syncthreads(); }
    float var = sh[0] * (1.f/DM);
    out[row*DM + tid] = dv * rsqrtf(var + eps) * g[tid] + b[tid];
}

// ---------------- generic tiled GEMM: C = f(A[M,K]@W[K,N]) ------------------
// mode 0: plain; 1: +bias; 2: softplus(+bias); 3: relu(acc)+res
__global__ void gemm_kernel(const float* __restrict__ A, int lda,
                            const float* __restrict__ W,
                            const float* __restrict__ bias,
                            const float* __restrict__ res,
                            float* __restrict__ C,
                            int M, int N, int K, int mode)
{
    __shared__ __align__(16) float As[16][68];
    __shared__ __align__(16) float Bs[16][68];
    int tid = threadIdx.x;
    int bm = blockIdx.y * 64;
    int bn = blockIdx.x * 64;
    int ty = tid >> 4, tx = tid & 15;
    float acc[4][4] = {};
    for (int kk = 0; kk < K; kk += 16) {
        #pragma unroll
        for (int i = 0; i < 4; i++) {
            int idx = tid + i*256;
            int r = idx >> 4, c = idx & 15;
            As[c][r] = A[(bm + r)*lda + kk + c];
        }
        #pragma unroll
        for (int i = 0; i < 4; i++) {
            int idx = tid + i*256;
            int r = idx >> 6, c = idx & 63;
            int n = bn + c;
            Bs[r][c] = (n < N) ? W[(kk + r)*N + n] : 0.f;
        }
        __syncthreads();
        #pragma unroll
        for (int k = 0; k < 16; k++) {
            float4 a4 = *reinterpret_cast<const float4*>(&As[k][ty*4]);
            float4 b4 = *reinterpret_cast<const float4*>(&Bs[k][tx*4]);
            float av[4] = {a4.x, a4.y, a4.z, a4.w};
            float bv[4] = {b4.x, b4.y, b4.z, b4.w};
            #pragma unroll
            for (int i = 0; i < 4; i++)
                #pragma unroll
                for (int j = 0; j < 4; j++)
                    acc[i][j] = fmaf(av[i], bv[j], acc[i][j]);
        }
        __syncthreads();
    }
    #pragma unroll
    for (int i = 0; i < 4; i++) {
        int r = bm + ty*4 + i;
        #pragma unroll
        for (int j = 0; j < 4; j++) {
            int cidx = bn + tx*4 + j;
            if (cidx < N) {
                float v = acc[i][j];
                if (mode == 1) v += bias[cidx];
                else if (mode == 2) {
                    v += bias[cidx];
                    v = (v > 20.f) ? v : log1pf(__expf(v));
                } else if (mode == 3) {
                    v = fmaxf(v, 0.f) + res[r*N + cidx];
                }
                C[r*N + cidx] = v;
            }
        }
    }
}

// ---------------- causal depthwise conv (K=4) + SiLU on first half of xz ----
__global__ void conv_silu_kernel(const float* __restrict__ xz,
                                 const float* __restrict__ cw,
                                 const float* __restrict__ cb,
                                 float* __restrict__ xc)
{
    int b = blockIdx.x;
    int d = blockIdx.y*128 + threadIdx.x;
    float w0 = cw[d*4+0], w1 = cw[d*4+1], w2 = cw[d*4+2], w3 = cw[d*4+3];
    float bias = cb[d];
    float x0 = 0.f, x1 = 0.f, x2 = 0.f;
    const float* src = xz + (size_t)b*LL*2*DI + d;
    float* dst = xc + (size_t)b*LL*DI + d;
    for (int t = 0; t < LL; t++) {
        float x3 = src[(size_t)t*2*DI];
        float v = fmaf(x0,w0, fmaf(x1,w1, fmaf(x2,w2, fmaf(x3,w3, bias))));
        float s = 1.f / (1.f + __expf(-v));
        dst[(size_t)t*DI] = v * s;
        x0 = x1; x1 = x2; x2 = x3;
    }
}

// ---------------- selective scan, both branches in one launch ---------------
struct ScanArgs {
    const float* dt[2];
    const float* xc[2];
    const float* xdbl[2];
    const float* Alog[2];
    const float* Dp[2];
    const float* xz[2];
    float* y[2];
};

__global__ void scan_kernel(ScanArgs a)
{
    int p = blockIdx.z;
    int b = blockIdx.x;
    int d = blockIdx.y*128 + threadIdx.x;
    __shared__ __align__(16) float4 Bsm[LL][4];
    __shared__ __align__(16) float4 Csm[LL][4];
    {
        const float* xd = a.xdbl[p] + (size_t)b*LL*48;
        float* Bf = (float*)Bsm;
        float* Cf = (float*)Csm;
        for (int i = threadIdx.x; i < LL*16; i += 128) {
            int t = i >> 4, j = i & 15;
            Bf[t*16+j] = xd[t*48 + 16 + j];
            Cf[t*16+j] = xd[t*48 + 32 + j];
        }
    }
    __syncthreads();
    float nA[16];
    #pragma unroll
    for (int s = 0; s < 16; s++) nA[s] = -__expf(a.Alog[p][d*16 + s]);
    float Dv = a.Dp[p][d];
    float h[16];
    #pragma unroll
    for (int s = 0; s < 16; s++) h[s] = 0.f;
    const float* dtp = a.dt[p] + (size_t)b*LL*DI + d;
    const float* xcp = a.xc[p] + (size_t)b*LL*DI + d;
    const float* zp  = a.xz[p] + (size_t)b*LL*2*DI + DI + d;
    float* yp        = a.y[p]  + (size_t)b*LL*DI + d;
    for (int t = 0; t < LL; t++) {
        float dtv = dtp[(size_t)t*DI];
        float xcv = xcp[(size_t)t*DI];
        float dbx = dtv * xcv;
        float Bv[16], Cv[16];
        *(float4*)&Bv[0]  = Bsm[t][0]; *(float4*)&Bv[4]  = Bsm[t][1];
        *(float4*)&Bv[8]  = Bsm[t][2]; *(float4*)&Bv[12] = Bsm[t][3];
        *(float4*)&Cv[0]  = Csm[t][0]; *(float4*)&Cv[4]  = Csm[t][1];
        *(float4*)&Cv[8]  = Csm[t][2]; *(float4*)&Cv[12] = Csm[t][3];
        float yv = 0.f;
        #pragma unroll
        for (int s = 0; s < 16; s++) {
            float dA = __expf(dtv * nA[s]);
            h[s] = fmaf(dA, h[s], dbx * Bv[s]);
            yv = fmaf(h[s], Cv[s], yv);
        }
        float zv = zp[(size_t)t*2*DI];
        float sz = zv / (1.f + __expf(-zv));
        yp[(size_t)t*DI] = (yv + xcv * Dv) * sz;
    }
}

// ---------------- fusion gate -----------------------------------------------
__global__ void pool_kernel(const float* __restrict__ aa, const float* __restrict__ ee,
                            float* __restrict__ pooled)
{
    int b = blockIdx.x, n = threadIdx.x;
    float s = 0.f;
    for (int l = 0; l < LL; l++) {
        size_t idx = ((size_t)b*LL + l)*DM + n;
        s += aa[idx] + ee[idx];
    }
    pooled[b*DM + n] = s * (0.5f / LL);
}

__global__ void fw_kernel(const float* __restrict__ pooled, const float* __restrict__ W,
                          float* __restrict__ fw)
{
    int b = blockIdx.x, n = threadIdx.x;
    __shared__ float pr[DM];
    pr[n] = pooled[b*DM + n];
    __syncthreads();
    float s = 0.f;
    for (int k = 0; k < DM; k++) s = fmaf(pr[k], W[k*DM + n], s);
    fw[b*DM + n] = 1.f / (1.f + __expf(-s));
}

__global__ void final_kernel(const float* __restrict__ aa, const float* __restrict__ ee,
                             const float* __restrict__ ida, const float* __restrict__ ide,
                             const float* __restrict__ fw, float* __restrict__ out)
{
    int i = blockIdx.x*256 + threadIdx.x;        // 0 .. 524287
    int b = i >> 16;                              // / (L*DM)
    int n = i & (DM-1);
    float f = fw[b*DM + n];
    out[i] = aa[i]*f + ida[i];
    out[(size_t)MROWS*DM + i] = ee[i]*f + ide[i];
}

// ---------------- launch -----------------------------------------------------
extern "C" void kernel_launch(void* const* d_in, const int* in_sizes, int n_in,
                              void* d_out, int out_size)
{
    (void)in_sizes; (void)n_in; (void)out_size;
    const float* x[2]    = { (const float*)d_in[0], (const float*)d_in[1] };
    const float* lng[2], *lnb[2], *Win[2], *cw[2], *cb[2], *Wx[2], *Wdt[2],
               * bdt[2], *Alog[2], *Dp[2], *Wout[2];
    for (int p = 0; p < 2; p++) {
        int o = 2 + p*11;
        lng[p]  = (const float*)d_in[o+0];
        lnb[p]  = (const float*)d_in[o+1];
        Win[p]  = (const float*)d_in[o+2];
        cw[p]   = (const float*)d_in[o+3];
        cb[p]   = (const float*)d_in[o+4];
        Wx[p]   = (const float*)d_in[o+5];
        Wdt[p]  = (const float*)d_in[o+6];
        bdt[p]  = (const float*)d_in[o+7];
        Alog[p] = (const float*)d_in[o+8];
        Dp[p]   = (const float*)d_in[o+9];
        Wout[p] = (const float*)d_in[o+10];
    }
    const float* scW  = (const float*)d_in[24];
    const float* scb  = (const float*)d_in[25];
    const float* sclg = (const float*)d_in[26];
    const float* sclb = (const float*)d_in[27];
    const float* fW   = (const float*)d_in[28];
    float* out = (float*)d_out;

    float *lnx[2], *xz[2], *xc[2], *dt[2], *xdbl[2], *yb[2], *ab[2], *id[2], *tmp[2];
    float *pool, *fw;
    cudaGetSymbolAddress((void**)&lnx[0], g_lnx);   lnx[1] = lnx[0] + MROWS*DM;
    cudaGetSymbolAddress((void**)&xz[0],  g_xz);    xz[1]  = xz[0]  + MROWS*2*DI;
    cudaGetSymbolAddress((void**)&xc[0],  g_xc);    xc[1]  = xc[0]  + MROWS*DI;
    cudaGetSymbolAddress((void**)&dt[0],  g_dt);    dt[1]  = dt[0]  + MROWS*DI;
    cudaGetSymbolAddress((void**)&xdbl[0],g_xdbl);  xdbl[1]= xdbl[0]+ MROWS*48;
    cudaGetSymbolAddress((void**)&yb[0],  g_y);     yb[1]  = yb[0]  + MROWS*DI;
    cudaGetSymbolAddress((void**)&ab[0],  g_ab);    ab[1]  = ab[0]  + MROWS*DM;
    cudaGetSymbolAddress((void**)&id[0],  g_id);    id[1]  = id[0]  + MROWS*DM;
    cudaGetSymbolAddress((void**)&tmp[0], g_tmp);   tmp[1] = tmp[0] + MROWS*DM;
    cudaGetSymbolAddress((void**)&pool,   g_pool);
    cudaGetSymbolAddress((void**)&fw,     g_fw);

    for (int p = 0; p < 2; p++) {
        // block LN (eps 1e-6)
        ln_kernel<<<MROWS, DM>>>(x[p], lng[p], lnb[p], lnx[p], 1e-6f);
        // in_proj: lnx (2048,256) @ W_in (256,1024)
        gemm_kernel<<<dim3(1024/64, MROWS/64), 256>>>(lnx[p], DM, Win[p], nullptr, nullptr,
                                                      xz[p], MROWS, 2*DI, DM, 0);
        // shortcut: x @ sc_W + sc_b, then LN eps 1e-5
        gemm_kernel<<<dim3(DM/64, MROWS/64), 256>>>(x[p], DM, scW, scb, nullptr,
                                                    tmp[p], MROWS, DM, DM, 1);
        ln_kernel<<<MROWS, DM>>>(tmp[p], sclg, sclb, id[p], 1e-5f);
        // causal depthwise conv + silu
        conv_silu_kernel<<<dim3(BB, DI/128), 128>>>(xz[p], cw[p], cb[p], xc[p]);
        // x_dbl: xc (2048,512) @ W_x (512,48)
        gemm_kernel<<<dim3(1, MROWS/64), 256>>>(xc[p], DI, Wx[p], nullptr, nullptr,
                                                xdbl[p], MROWS, 48, DI, 0);
        // dt: softplus(x_dbl[:, :16] @ W_dt + b_dt)   (lda = 48)
        gemm_kernel<<<dim3(DI/64, MROWS/64), 256>>>(xdbl[p], 48, Wdt[p], bdt[p], nullptr,
                                                    dt[p], MROWS, DI, DTR, 2);
    }

    // selective scan (both branches), fused (y + xc*D)*silu(z) epilogue
    ScanArgs sa;
    for (int p = 0; p < 2; p++) {
        sa.dt[p] = dt[p]; sa.xc[p] = xc[p]; sa.xdbl[p] = xdbl[p];
        sa.Alog[p] = Alog[p]; sa.Dp[p] = Dp[p]; sa.xz[p] = xz[p]; sa.y[p] = yb[p];
    }
    scan_kernel<<<dim3(BB, DI/128, 2), 128>>>(sa);

    for (int p = 0; p < 2; p++) {
        // out_proj: y (2048,512) @ W_out (512,256); relu + residual x
        gemm_kernel<<<dim3(DM/64, MROWS/64), 256>>>(yb[p], DI, Wout[p], nullptr, x[p],
                                                    ab[p], MROWS, DM, DI, 3);
    }

    // fusion gate
    pool_kernel<<<BB, DM>>>(ab[0], ab[1], pool);
    fw_kernel<<<BB, DM>>>(pool, fW, fw);
    final_kernel<<<MROWS*DM/256, 256>>>(ab[0], ab[1], id[0], id[1], fw, out);
}